// round 9
// baseline (speedup 1.0000x reference)
#include <cuda_runtime.h>
#include <cstdint>

#define HDIM   1024
#define NHEADS 16
#define HEADD  64
#define BATCH  2
#define SEQ    2048
#define MTOK   (BATCH*SEQ)     // 4096 tokens

// Contract-dim storage permutation within each 8-col group: c -> [0,4,1,5,2,6,3,7]
// position. Lane pair {t, t+4} becomes adjacent {2t, 2t+1} -> LDS.64 fragment loads.
// Pure storage reordering: fragment register contents (and thus numerics) unchanged.
__device__ __forceinline__ int perm8(int c) { return ((c & 3) << 1) | (c >> 2); }

// ---------------- scratch (static device memory; no allocations) ----------------
__device__ float g_xn[MTOK*HDIM];                       // LN output, tf32, K-permuted
__device__ float g_q[BATCH*NHEADS*SEQ*HEADD];           // [bh, s, hd], tf32, hd-permuted
__device__ float g_k[BATCH*NHEADS*SEQ*HEADD];           // hd-permuted
__device__ float g_v[BATCH*NHEADS*SEQ*HEADD];           // NOT permuted (PV contract = kv rows)
__device__ float g_att[MTOK*HDIM];                      // tf32, feature-permuted
__device__ float g_wq[HDIM*HDIM], g_wk[HDIM*HDIM], g_wv[HDIM*HDIM], g_wo[HDIM*HDIM]; // K-permuted

// ---------------- helpers ----------------
__device__ __forceinline__ uint32_t f2tf32(float f) {
    uint32_t u;
    asm("cvt.rna.tf32.f32 %0, %1;" : "=r"(u) : "f"(f));
    return u;
}
__device__ __forceinline__ float f2tf32f(float f) { return __uint_as_float(f2tf32(f)); }

__device__ __forceinline__ void mma_tf32(float* c, const uint32_t* a, const uint32_t* b) {
    asm volatile(
        "mma.sync.aligned.m16n8k8.row.col.f32.tf32.tf32.f32 "
        "{%0,%1,%2,%3}, {%4,%5,%6,%7}, {%8,%9}, {%0,%1,%2,%3};\n"
        : "+f"(c[0]), "+f"(c[1]), "+f"(c[2]), "+f"(c[3])
        : "r"(a[0]), "r"(a[1]), "r"(a[2]), "r"(a[3]), "r"(b[0]), "r"(b[1]));
}

// .cg: bypass L1 (every staged tile is read from GMEM exactly once), keep L2.
#define CP_ASYNC16(dst_u32, src_ptr) \
    asm volatile("cp.async.cg.shared.global [%0], [%1], 16;\n" :: "r"(dst_u32), "l"(src_ptr))
#define CP_COMMIT() asm volatile("cp.async.commit_group;\n")

// ---------------- fused prep: weight round+permute AND LayerNorm, one launch ----
// Blocks [0, 4096): weight rounding, float4 loads, 4 elems/thread (1M float4 over
//                   4 matrices of 2^18 float4 each).
// Blocks [4096, 8192): LN, one block per token.
// The two halves touch disjoint data; both only feed gemm_qkv.
#define PREP_WBLOCKS 4096
#define PREP_BLOCKS  (PREP_WBLOCKS + MTOK)

__global__ __launch_bounds__(256) void prep_kernel(
    const float* __restrict__ wa, const float* __restrict__ wb,
    const float* __restrict__ wc, const float* __restrict__ wd,
    float* __restrict__ oa, float* __restrict__ ob,
    float* __restrict__ oc, float* __restrict__ od,
    const float* __restrict__ x, const float* __restrict__ gamma,
    const float* __restrict__ beta, float* __restrict__ xn) {
    if (blockIdx.x < PREP_WBLOCKS) {
        // ---- weight rounding + K-permute, float4-vectorized ----
        int fi   = blockIdx.x * 256 + threadIdx.x;   // 0 .. 2^20-1 (float4 index)
        int sel  = fi >> 18;                         // 2^18 float4 per matrix
        int off4 = fi & 0x3FFFF;
        int off  = off4 << 2;                        // element offset, multiple of 4
        const float* s = (sel == 0) ? wa : (sel == 1) ? wb : (sel == 2) ? wc : wd;
        float* dst     = (sel == 0) ? oa : (sel == 1) ? ob : (sel == 2) ? oc : od;
        float4 v = ((const float4*)s)[off4];
        // elements off..off+3 stay in one 8-group half: permuted positions are
        // base + {0,2,4,6} (+1 if upper half) — same pattern as the LN path.
        float* d = dst + (off & ~7) + ((off & 4) ? 1 : 0);
        d[0] = f2tf32f(v.x);
        d[2] = f2tf32f(v.y);
        d[4] = f2tf32f(v.z);
        d[6] = f2tf32f(v.w);
        return;
    }
    // ---- LayerNorm (identical math to previous rounds) ----
    int row = blockIdx.x - PREP_WBLOCKS;
    const float4 v = ((const float4*)(x + (size_t)row * HDIM))[threadIdx.x];
    float s  = v.x + v.y + v.z + v.w;
    float sq = v.x * v.x + v.y * v.y + v.z * v.z + v.w * v.w;
    #pragma unroll
    for (int o = 16; o; o >>= 1) {
        s  += __shfl_xor_sync(0xffffffffu, s, o);
        sq += __shfl_xor_sync(0xffffffffu, sq, o);
    }
    __shared__ float red[16];
    int w = threadIdx.x >> 5, l = threadIdx.x & 31;
    if (l == 0) { red[w] = s; red[w + 8] = sq; }
    __syncthreads();
    float ts = 0.f, tq = 0.f;
    #pragma unroll
    for (int i = 0; i < 8; i++) { ts += red[i]; tq += red[i + 8]; }
    float mu  = ts * (1.0f / HDIM);
    float var = tq * (1.0f / HDIM) - mu * mu;
    float inv = rsqrtf(var + 1e-5f);
    const float4 g4 = ((const float4*)gamma)[threadIdx.x];
    const float4 b4 = ((const float4*)beta)[threadIdx.x];
    int c0 = threadIdx.x * 4;
    float* dst = xn + (size_t)row * HDIM + (c0 & ~7) + ((c0 & 4) ? 1 : 0);
    dst[0] = f2tf32f((v.x - mu) * inv * g4.x + b4.x);
    dst[2] = f2tf32f((v.y - mu) * inv * g4.y + b4.y);
    dst[4] = f2tf32f((v.z - mu) * inv * g4.z + b4.z);
    dst[6] = f2tf32f((v.w - mu) * inv * g4.w + b4.w);
}

// ---------------- TF32 GEMM: C = A[M,K] * B[N,K]^T  (A,B K-permuted) ------------
// 3-stage cp.async pipeline, one __syncthreads per K-tile. Fragment loads are
// LDS.64 thanks to the K-permutation; GST=24 gives conflict-free float2 phases.
#define BM 128
#define BN 128
#define BK 16
#define GST 24                      // stride: conflict-free LDS.64, 16B-aligned rows
#define GTILE (BM*GST)
#define GSTAGES 3
#define GEMM_SMEM (GSTAGES*2*GTILE*4)   // 73728 B dynamic

__device__ __forceinline__ void qkv_store(float* __restrict__ C, int row, int col,
                                          float val, int permute_hd) {
    int b  = row >> 11;         // / SEQ
    int s  = row & (SEQ - 1);
    int h  = col >> 6;
    int hd = col & 63;
    if (permute_hd) hd = (hd & ~7) | perm8(hd & 7);
    C[(((b * NHEADS + h) * SEQ + s) << 6) + hd] = f2tf32f(val);
}

struct GemmCore {
    float acc[4][4][4];
    int tid, warp, lane, g, t, wm, wn;

    __device__ __forceinline__ void init(int tid_) {
        tid = tid_; warp = tid >> 5; lane = tid & 31;
        g = lane >> 2; t = lane & 3;
        wm = warp >> 2; wn = warp & 3;           // 2 x 4 warp grid
        #pragma unroll
        for (int mi = 0; mi < 4; mi++)
            #pragma unroll
            for (int ni = 0; ni < 4; ni++)
                #pragma unroll
                for (int j = 0; j < 4; j++) acc[mi][ni][j] = 0.f;
    }

    __device__ __forceinline__ void run(const float* __restrict__ A,
                                        const float* __restrict__ Bw,
                                        float* __restrict__ smem,
                                        int bm0, int bn0) {
        float* As[GSTAGES] = { smem, smem + GTILE, smem + 2 * GTILE };
        float* Bs[GSTAGES] = { smem + 3 * GTILE, smem + 4 * GTILE, smem + 5 * GTILE };

        auto issue = [&](int kt, int buf) {
            int k0 = kt * BK;
            #pragma unroll
            for (int j = 0; j < 2; j++) {
                int f = tid + j * 256;               // 512 float4 per tile
                int row = f >> 2;
                int col = (f & 3) << 2;
                const float* srcA = A + (size_t)(bm0 + row) * HDIM + k0 + col;
                const float* srcB = Bw + (size_t)(bn0 + row) * HDIM + k0 + col;
                uint32_t dA = (uint32_t)__cvta_generic_to_shared(&As[buf][row * GST + col]);
                uint32_t dB = (uint32_t)__cvta_generic_to_shared(&Bs[buf][row * GST + col]);
                CP_ASYNC16(dA, srcA);
                CP_ASYNC16(dB, srcB);
            }
            CP_COMMIT();
        };

        const int NT = HDIM / BK;   // 64
        issue(0, 0);
        issue(1, 1);
        for (int kt = 0; kt < NT; kt++) {
            if (kt + 1 < NT) {
                asm volatile("cp.async.wait_group 1;\n");   // groups <= kt complete
            } else {
                asm volatile("cp.async.wait_group 0;\n");   // last group complete
            }
            __syncthreads();
            if (kt + 2 < NT) issue(kt + 2, (kt + 2) % GSTAGES);

            const float* pa = As[kt % GSTAGES];
            const float* pb = Bs[kt % GSTAGES];
            #pragma unroll
            for (int ks = 0; ks < 2; ks++) {
                int kk = ks * 8;
                uint32_t af[4][4], bf[4][2];
                #pragma unroll
                for (int mi = 0; mi < 4; mi++) {
                    int rm = wm * 64 + mi * 16;
                    float2 a0 = *(const float2*)(pa + (rm + g) * GST + kk + 2 * t);
                    float2 a1 = *(const float2*)(pa + (rm + g + 8) * GST + kk + 2 * t);
                    af[mi][0] = __float_as_uint(a0.x);
                    af[mi][2] = __float_as_uint(a0.y);
                    af[mi][1] = __float_as_uint(a1.x);
                    af[mi][3] = __float_as_uint(a1.y);
                }
                #pragma unroll
                for (int ni = 0; ni < 4; ni++) {
                    int rn = wn * 32 + ni * 8;
                    float2 b0 = *(const float2*)(pb + (rn + g) * GST + kk + 2 * t);
                    bf[ni][0] = __float_as_uint(b0.x);
                    bf[ni][1] = __float_as_uint(b0.y);
                }
                #pragma unroll
                for (int mi = 0; mi < 4; mi++)
                    #pragma unroll
                    for (int ni = 0; ni < 4; ni++) mma_tf32(acc[mi][ni], af[mi], bf[ni]);
            }
        }
    }
};

__global__ __launch_bounds__(256) void gemm_qkv(
    const float* __restrict__ A,
    const float* __restrict__ Wq, const float* __restrict__ Wk, const float* __restrict__ Wv,
    float* __restrict__ Oq, float* __restrict__ Ok, float* __restrict__ Ov) {
    extern __shared__ __align__(16) float gsm[];
    int z = blockIdx.z;
    const float* Bw = (z == 0) ? Wq : (z == 1) ? Wk : Wv;
    float* Cout     = (z == 0) ? Oq : (z == 1) ? Ok : Ov;
    int permute_hd  = (z != 2);     // Q,K: hd is the S-mma contract dim; V: not
    int bm0 = blockIdx.y * BM, bn0 = blockIdx.x * BN;

    GemmCore core;
    core.init(threadIdx.x);
    core.run(A, Bw, gsm, bm0, bn0);

    #pragma unroll
    for (int mi = 0; mi < 4; mi++) {
        #pragma unroll
        for (int ni = 0; ni < 4; ni++) {
            int row0 = bm0 + core.wm * 64 + mi * 16 + core.g;
            int col0 = bn0 + core.wn * 32 + ni * 8 + 2 * core.t;
            if (permute_hd) {
                qkv_store(Cout, row0,     col0,     core.acc[mi][ni][0], 1);
                qkv_store(Cout, row0,     col0 + 1, core.acc[mi][ni][1], 1);
                qkv_store(Cout, row0 + 8, col0,     core.acc[mi][ni][2], 1);
                qkv_store(Cout, row0 + 8, col0 + 1, core.acc[mi][ni][3], 1);
            } else {
                // V: hd unpermuted -> contiguous pair, float2 stores
                int b = row0 >> 11, h = col0 >> 6, hd = col0 & 63;
                int s0 = row0 & (SEQ - 1);
                float* base = Cout + (((size_t)(b * NHEADS + h) * SEQ) << 6) + hd;
                float2 v0 = { f2tf32f(core.acc[mi][ni][0]), f2tf32f(core.acc[mi][ni][1]) };
                float2 v1 = { f2tf32f(core.acc[mi][ni][2]), f2tf32f(core.acc[mi][ni][3]) };
                *(float2*)(base + ((size_t)s0 << 6))       = v0;
                *(float2*)(base + ((size_t)(s0 + 8) << 6)) = v1;
            }
        }
    }
}

__global__ __launch_bounds__(256) void gemm_oproj(
    const float* __restrict__ A, const float* __restrict__ Bw, float* __restrict__ Cout,
    const float* __restrict__ bias, const float* __restrict__ resid) {
    extern __shared__ __align__(16) float gsm[];
    int bm0 = blockIdx.y * BM, bn0 = blockIdx.x * BN;

    GemmCore core;
    core.init(threadIdx.x);
    core.run(A, Bw, gsm, bm0, bn0);

    // output N-dim is unpermuted: normal contiguous stores
    #pragma unroll
    for (int mi = 0; mi < 4; mi++) {
        #pragma unroll
        for (int ni = 0; ni < 4; ni++) {
            int row0 = bm0 + core.wm * 64 + mi * 16 + core.g;
            int col0 = bn0 + core.wn * 32 + ni * 8 + 2 * core.t;
            size_t i0 = (size_t)row0 * HDIM + col0;
            size_t i1 = (size_t)(row0 + 8) * HDIM + col0;
            float2 b2 = *(const float2*)(bias + col0);
            float2 r0 = *(const float2*)(resid + i0);
            float2 r1 = *(const float2*)(resid + i1);
            float2 o0, o1;
            o0.x = core.acc[mi][ni][0] + b2.x + r0.x;
            o0.y = core.acc[mi][ni][1] + b2.y + r0.y;
            o1.x = core.acc[mi][ni][2] + b2.x + r1.x;
            o1.y = core.acc[mi][ni][3] + b2.y + r1.y;
            *(float2*)(Cout + i0) = o0;
            *(float2*)(Cout + i1) = o1;
        }
    }
}

// ---------------- flash attention: BQ=128, BKV=64, HD=64, 8 warps ----------------
// Q/K hd-permuted and P kv-permuted in storage -> LDS.64 fragment loads.
// K/V double-buffered via cp.async. ONE __syncthreads per KV-iteration:
// wait_group 0 first (only the needed group is pending), barrier, THEN issue the
// next prefetch — the single barrier also proves all warps finished reading the
// buffer being overwritten. Psm is warp-private rows: __syncwarp suffices.
#define BQ  128
#define BKV 64
#define KSW 72   // K tile row stride: conflict-free LDS.64
#define VSW 72   // V tile row stride: conflict-free scalar B-frag loads
#define PSW 72   // P / Q-stage row stride
#define FLASH_SMEM ((2*64*KSW + 2*64*VSW + 128*PSW) * 4)   // 110592 B

__global__ __launch_bounds__(256) void flash_kernel(
    const float* __restrict__ Qb, const float* __restrict__ Kb,
    const float* __restrict__ Vb, float* __restrict__ Ob) {
    extern __shared__ __align__(16) float sm[];
    float* Ksm[2] = { sm, sm + 64 * KSW };
    float* Vsm[2] = { sm + 2 * 64 * KSW, sm + 2 * 64 * KSW + 64 * VSW };
    float* Psm = sm + 2 * 64 * KSW + 2 * 64 * VSW;   // [128][PSW] (Q staging, then P)

    int tid = threadIdx.x, warp = tid >> 5, lane = tid & 31;
    int g = lane >> 2, t = lane & 3;
    int bh = blockIdx.y, qt = blockIdx.x;
    int r0 = warp * 16;
    int pc0 = perm8(2 * t), pc1 = perm8(2 * t + 1);  // P write positions (C-frag cols)

    const float* Qp = Qb + ((size_t)bh * SEQ + qt * BQ) * HEADD;
    const float* Kp = Kb + (size_t)bh * SEQ * HEADD;
    const float* Vp = Vb + (size_t)bh * SEQ * HEADD;

    auto loadKV = [&](int kt, int buf) {
        #pragma unroll
        for (int j = 0; j < 4; j++) {
            int f = tid + j * 256;    // 1024 float4 = 64x16
            int row = f >> 4, c4 = f & 15;
            const float* srcK = Kp + (size_t)(kt * BKV + row) * HEADD + c4 * 4;
            const float* srcV = Vp + (size_t)(kt * BKV + row) * HEADD + c4 * 4;
            uint32_t dK = (uint32_t)__cvta_generic_to_shared(Ksm[buf] + row * KSW + c4 * 4);
            uint32_t dV = (uint32_t)__cvta_generic_to_shared(Vsm[buf] + row * VSW + c4 * 4);
            CP_ASYNC16(dK, srcK);
            CP_ASYNC16(dV, srcV);
        }
        CP_COMMIT();
    };

    // prologue: issue first K/V tile load, then stage Q through Psm while it flies
    loadKV(0, 0);

    #pragma unroll
    for (int j = 0; j < 8; j++) {
        int f = tid + j * 256;        // 2048 float4 = 128x16
        int row = f >> 4, c4 = f & 15;
        *(float4*)(Psm + row * PSW + c4 * 4) = *(const float4*)(Qp + row * HEADD + c4 * 4);
    }
    __syncthreads();
    // pull Q A-fragments via LDS.64 (hd-permuted); pre-scaled by 1/sqrt(64)=0.125
    uint32_t qa[8][4];
    #pragma unroll
    for (int ks = 0; ks < 8; ks++) {
        int kk = ks * 8;
        float2 q0 = *(const float2*)(Psm + (r0 + g) * PSW + kk + 2 * t);
        float2 q1 = *(const float2*)(Psm + (r0 + g + 8) * PSW + kk + 2 * t);
        qa[ks][0] = __float_as_uint(0.125f * q0.x);
        qa[ks][2] = __float_as_uint(0.125f * q0.y);
        qa[ks][1] = __float_as_uint(0.125f * q1.x);
        qa[ks][3] = __float_as_uint(0.125f * q1.y);
    }
    // no barrier needed here: Psm rows are warp-private from here on

    float o[8][4];
    #pragma unroll
    for (int ni = 0; ni < 8; ni++)
        #pragma unroll
        for (int j = 0; j < 4; j++) o[ni][j] = 0.f;
    float m0 = -1e30f, m1 = -1e30f, l0 = 0.f, l1 = 0.f;

    const int NT = SEQ / BKV;   // 32
    for (int kt = 0; kt < NT; kt++) {
        // only the group we need is pending at this point -> wait_group 0 is exact
        asm volatile("cp.async.wait_group 0;\n");
        __syncthreads();   // data visible to all warps + all warps done with old buffer
        if (kt + 1 < NT) loadKV(kt + 1, (kt + 1) & 1);

        const float* Kc = Ksm[kt & 1];
        const float* Vc = Vsm[kt & 1];

        // S = Q * K^T  (16 x 64 per warp); K B-frags via LDS.64
        float s[8][4];
        #pragma unroll
        for (int ni = 0; ni < 8; ni++)
            #pragma unroll
            for (int j = 0; j < 4; j++) s[ni][j] = 0.f;
        #pragma unroll
        for (int ks = 0; ks < 8; ks++) {
            int kk = ks * 8;
            #pragma unroll
            for (int ni = 0; ni < 8; ni++) {
                float2 kb = *(const float2*)(Kc + (ni * 8 + g) * KSW + kk + 2 * t);
                uint32_t bf[2];
                bf[0] = __float_as_uint(kb.x);
                bf[1] = __float_as_uint(kb.y);
                mma_tf32(s[ni], qa[ks], bf);
            }
        }

        // online softmax (rows g and g+8); P stored kv-permuted
        float mx0 = -1e30f, mx1 = -1e30f;
        #pragma unroll
        for (int ni = 0; ni < 8; ni++) {
            mx0 = fmaxf(mx0, fmaxf(s[ni][0], s[ni][1]));
            mx1 = fmaxf(mx1, fmaxf(s[ni][2], s[ni][3]));
        }
        mx0 = fmaxf(mx0, __shfl_xor_sync(0xffffffffu, mx0, 1));
        mx0 = fmaxf(mx0, __shfl_xor_sync(0xffffffffu, mx0, 2));
        mx1 = fmaxf(mx1, __shfl_xor_sync(0xffffffffu, mx1, 1));
        mx1 = fmaxf(mx1, __shfl_xor_sync(0xffffffffu, mx1, 2));
        float mn0 = fmaxf(m0, mx0), mn1 = fmaxf(m1, mx1);
        float al0 = __expf(m0 - mn0), al1 = __expf(m1 - mn1);
        float sum0 = 0.f, sum1 = 0.f;
        #pragma unroll
        for (int ni = 0; ni < 8; ni++) {
            float p0 = __expf(s[ni][0] - mn0);
            float p1 = __expf(s[ni][1] - mn0);
            float p2 = __expf(s[ni][2] - mn1);
            float p3 = __expf(s[ni][3] - mn1);
            sum0 += p0 + p1;
            sum1 += p2 + p3;
            int gb = ni * 8;
            Psm[(r0 + g) * PSW + gb + pc0]     = f2tf32f(p0);
            Psm[(r0 + g) * PSW + gb + pc1]     = f2tf32f(p1);
            Psm[(r0 + g + 8) * PSW + gb + pc0] = f2tf32f(p2);
            Psm[(r0 + g + 8) * PSW + gb + pc1] = f2tf32f(p3);
        }
        sum0 += __shfl_xor_sync(0xffffffffu, sum0, 1);
        sum0 += __shfl_xor_sync(0xffffffffu, sum0, 2);
        sum1 += __shfl_xor_sync(0xffffffffu, sum1, 1);
        sum1 += __shfl_xor_sync(0xffffffffu, sum1, 2);
        l0 = l0 * al0 + sum0;
        l1 = l1 * al1 + sum1;
        m0 = mn0; m1 = mn1;
        #pragma unroll
        for (int ni = 0; ni < 8; ni++) {
            o[ni][0] *= al0; o[ni][1] *= al0;
            o[ni][2] *= al1; o[ni][3] *= al1;
        }
        __syncwarp();   // Psm rows are warp-private: warp-level ordering suffices

        // O += P * V; P A-frags via LDS.64 (kv-permuted), V scalar (conflict-free)
        #pragma unroll
        for (int ks = 0; ks < 8; ks++) {
            int kk = ks * 8;
            float2 pA = *(const float2*)(Psm + (r0 + g) * PSW + kk + 2 * t);
            float2 pB = *(const float2*)(Psm + (r0 + g + 8) * PSW + kk + 2 * t);
            uint32_t pf[4];
            pf[0] = __float_as_uint(pA.x);
            pf[2] = __float_as_uint(pA.y);
            pf[1] = __float_as_uint(pB.x);
            pf[3] = __float_as_uint(pB.y);
            #pragma unroll
            for (int ni = 0; ni < 8; ni++) {
                uint32_t vf[2];
                vf[0] = __float_as_uint(Vc[(kk + t) * VSW + ni * 8 + g]);
                vf[1] = __float_as_uint(Vc[(kk + t + 4) * VSW + ni * 8 + g]);
                mma_tf32(o[ni], pf, vf);
            }
        }
        // no trailing barrier: next iteration's top barrier provides the
        // cross-warp ordering before the prefetch overwrites this buffer
    }

    // epilogue: normalize; write g_att feature-permuted (tf32: feeds O-proj mma)
    float i0 = 1.0f / l0, i1 = 1.0f / l1;
    int b = bh / NHEADS, h = bh % NHEADS;
    int tok0 = b * SEQ + qt * BQ + r0;
    #pragma unroll
    for (int ni = 0; ni < 8; ni++) {
        int colb = h * 64 + ni * 8;
        size_t ia = (size_t)(tok0 + g) * HDIM + colb;
        size_t ib = (size_t)(tok0 + g + 8) * HDIM + colb;
        Ob[ia + pc0] = f2tf32f(o[ni][0] * i0);
        Ob[ia + pc1] = f2tf32f(o[ni][1] * i0);
        Ob[ib + pc0] = f2tf32f(o[ni][2] * i1);
        Ob[ib + pc1] = f2tf32f(o[ni][3] * i1);
    }
}

// ---------------- launch ----------------
extern "C" void kernel_launch(void* const* d_in, const int* in_sizes, int n_in,
                              void* d_out, int out_size) {
    const float* x     = (const float*)d_in[0];
    const float* Wq    = (const float*)d_in[1];
    const float* Wk    = (const float*)d_in[2];
    const float* Wv    = (const float*)d_in[3];
    const float* Wo    = (const float*)d_in[4];
    const float* bo    = (const float*)d_in[5];
    const float* gamma = (const float*)d_in[6];
    const float* beta  = (const float*)d_in[7];
    float* out = (float*)d_out;

    float *p_xn, *p_q, *p_k, *p_v, *p_att, *p_wq, *p_wk, *p_wv, *p_wo;
    cudaGetSymbolAddress((void**)&p_xn, g_xn);
    cudaGetSymbolAddress((void**)&p_q, g_q);
    cudaGetSymbolAddress((void**)&p_k, g_k);
    cudaGetSymbolAddress((void**)&p_v, g_v);
    cudaGetSymbolAddress((void**)&p_att, g_att);
    cudaGetSymbolAddress((void**)&p_wq, g_wq);
    cudaGetSymbolAddress((void**)&p_wk, g_wk);
    cudaGetSymbolAddress((void**)&p_wv, g_wv);
    cudaGetSymbolAddress((void**)&p_wo, g_wo);

    cudaFuncSetAttribute(flash_kernel, cudaFuncAttributeMaxDynamicSharedMemorySize, FLASH_SMEM);
    cudaFuncSetAttribute(gemm_qkv,   cudaFuncAttributeMaxDynamicSharedMemorySize, GEMM_SMEM);
    cudaFuncSetAttribute(gemm_oproj, cudaFuncAttributeMaxDynamicSharedMemorySize, GEMM_SMEM);

    prep_kernel<<<PREP_BLOCKS, 256>>>(Wq, Wk, Wv, Wo, p_wq, p_wk, p_wv, p_wo,
                                      x, gamma, beta, p_xn);

    dim3 gq(HDIM / BN, MTOK / BM, 3);   // (8, 32, 3) fused QKV
    gemm_qkv<<<gq, 256, GEMM_SMEM>>>(p_xn, p_wq, p_wk, p_wv, p_q, p_k, p_v);

    flash_kernel<<<dim3(SEQ / BQ, BATCH * NHEADS), 256, FLASH_SMEM>>>(p_q, p_k, p_v, p_att);

    dim3 go(HDIM / BN, MTOK / BM);      // (8, 32)
    gemm_oproj<<<go, 256, GEMM_SMEM>>>(p_att, p_wo, out, bo, x);
}

// round 10
// speedup vs baseline: 1.4622x; 1.4622x over previous
#include <cuda_runtime.h>
#include <cuda_bf16.h>
#include <cstdint>

#define HDIM   1024
#define NHEADS 16
#define HEADD  64
#define BATCH  2
#define SEQ    2048
#define MTOK   (BATCH*SEQ)     // 4096 tokens

// ---------------- scratch (static device memory; no allocations) ----------------
// stored as uint16_t (bf16 bits) to keep device-global declarations trivial
__device__ __align__(16) uint16_t g_xn[MTOK*HDIM];                 // LN out, bf16
__device__ __align__(16) uint16_t g_q [BATCH*NHEADS*SEQ*HEADD];    // [bh][s][hd], pre-scaled 0.125
__device__ __align__(16) uint16_t g_k [BATCH*NHEADS*SEQ*HEADD];    // [bh][s][hd]
__device__ __align__(16) uint16_t g_v [BATCH*NHEADS*HEADD*SEQ];    // [bh][hd][s]  TRANSPOSED
__device__ __align__(16) uint16_t g_att[MTOK*HDIM];                // [tok][feat], bf16
__device__ __align__(16) uint16_t g_wq[HDIM*HDIM], g_wk[HDIM*HDIM];
__device__ __align__(16) uint16_t g_wv[HDIM*HDIM], g_wo[HDIM*HDIM];

// ---------------- helpers ----------------
__device__ __forceinline__ uint32_t f2bf2(float lo, float hi) {
    __nv_bfloat162 h = __floats2bfloat162_rn(lo, hi);   // x=lo (low 16 bits), y=hi
    return *reinterpret_cast<uint32_t*>(&h);
}
__device__ __forceinline__ uint16_t f2bf(float v) {
    __nv_bfloat16 h = __float2bfloat16_rn(v);
    return *reinterpret_cast<uint16_t*>(&h);
}

// bf16 m16n8k16: A={a0..a3}, B={b0,b1}, C=f32x4
__device__ __forceinline__ void mma_bf16(float* c, const uint32_t* a, const uint32_t* b) {
    asm volatile(
        "mma.sync.aligned.m16n8k16.row.col.f32.bf16.bf16.f32 "
        "{%0,%1,%2,%3}, {%4,%5,%6,%7}, {%8,%9}, {%0,%1,%2,%3};\n"
        : "+f"(c[0]), "+f"(c[1]), "+f"(c[2]), "+f"(c[3])
        : "r"(a[0]), "r"(a[1]), "r"(a[2]), "r"(a[3]), "r"(b[0]), "r"(b[1]));
}

#define CP_ASYNC16(dst_u32, src_ptr) \
    asm volatile("cp.async.cg.shared.global [%0], [%1], 16;\n" :: "r"(dst_u32), "l"(src_ptr))
#define CP_COMMIT() asm volatile("cp.async.commit_group;\n")

// ---------------- fused prep: weight fp32->bf16 AND LayerNorm ----------------
// Blocks [0, 4096): weights (1M float4; 4 elems/thread). Blocks [4096, 8192): LN.
#define PREP_WBLOCKS 4096
#define PREP_BLOCKS  (PREP_WBLOCKS + MTOK)

__global__ __launch_bounds__(256) void prep_kernel(
    const float* __restrict__ wa, const float* __restrict__ wb,
    const float* __restrict__ wc, const float* __restrict__ wd,
    uint16_t* __restrict__ oa, uint16_t* __restrict__ ob,
    uint16_t* __restrict__ oc, uint16_t* __restrict__ od,
    const float* __restrict__ x, const float* __restrict__ gamma,
    const float* __restrict__ beta, uint16_t* __restrict__ xn) {
    if (blockIdx.x < PREP_WBLOCKS) {
        int fi   = blockIdx.x * 256 + threadIdx.x;   // float4 index 0..2^20-1
        int sel  = fi >> 18;                         // 2^18 float4 per matrix
        int off4 = fi & 0x3FFFF;
        int off  = off4 << 2;
        const float* s = (sel == 0) ? wa : (sel == 1) ? wb : (sel == 2) ? wc : wd;
        uint16_t* dst  = (sel == 0) ? oa : (sel == 1) ? ob : (sel == 2) ? oc : od;
        float4 v = ((const float4*)s)[off4];
        uint2 p;
        p.x = f2bf2(v.x, v.y);
        p.y = f2bf2(v.z, v.w);
        *(uint2*)(dst + off) = p;                    // 8B store, aligned
        return;
    }
    // ---- LayerNorm (fp32 math, bf16 out) ----
    int row = blockIdx.x - PREP_WBLOCKS;
    const float4 v = ((const float4*)(x + (size_t)row * HDIM))[threadIdx.x];
    float s  = v.x + v.y + v.z + v.w;
    float sq = v.x * v.x + v.y * v.y + v.z * v.z + v.w * v.w;
    #pragma unroll
    for (int o = 16; o; o >>= 1) {
        s  += __shfl_xor_sync(0xffffffffu, s, o);
        sq += __shfl_xor_sync(0xffffffffu, sq, o);
    }
    __shared__ float red[16];
    int w = threadIdx.x >> 5, l = threadIdx.x & 31;
    if (l == 0) { red[w] = s; red[w + 8] = sq; }
    __syncthreads();
    float ts = 0.f, tq = 0.f;
    #pragma unroll
    for (int i = 0; i < 8; i++) { ts += red[i]; tq += red[i + 8]; }
    float mu  = ts * (1.0f / HDIM);
    float var = tq * (1.0f / HDIM) - mu * mu;
    float inv = rsqrtf(var + 1e-5f);
    const float4 g4 = ((const float4*)gamma)[threadIdx.x];
    const float4 b4 = ((const float4*)beta)[threadIdx.x];
    uint2 p;
    p.x = f2bf2((v.x - mu) * inv * g4.x + b4.x, (v.y - mu) * inv * g4.y + b4.y);
    p.y = f2bf2((v.z - mu) * inv * g4.z + b4.z, (v.w - mu) * inv * g4.w + b4.w);
    *(uint2*)(xn + (size_t)row * HDIM + threadIdx.x * 4) = p;
}

// ---------------- bf16 GEMM: C = A[M,K] * B[N,K]^T ----------------
// BK=16 (one m16n8k16 K-step per tile), 3-stage cp.async, one barrier per tile.
// Row stride 24 bf16 = 48 B -> LDS.32 frag loads conflict-free (banks 12g+t).
#define BM 128
#define BN 128
#define BK 16
#define GST 24                         // bf16 units per row (16 data + 8 pad)
#define GTILE (BM*GST)                 // bf16 units per stage buffer
#define GSTAGES 3
#define GEMM_SMEM (GSTAGES*2*GTILE*2)  // 36864 B dynamic

struct GemmCore {
    float acc[4][4][4];
    int tid, warp, lane, g, t, wm, wn;

    __device__ __forceinline__ void init(int tid_) {
        tid = tid_; warp = tid >> 5; lane = tid & 31;
        g = lane >> 2; t = lane & 3;
        wm = warp >> 2; wn = warp & 3;             // 2 x 4 warp grid
        #pragma unroll
        for (int mi = 0; mi < 4; mi++)
            #pragma unroll
            for (int ni = 0; ni < 4; ni++)
                #pragma unroll
                for (int j = 0; j < 4; j++) acc[mi][ni][j] = 0.f;
    }

    __device__ __forceinline__ void run(const uint16_t* __restrict__ A,
                                        const uint16_t* __restrict__ Bw,
                                        __nv_bfloat16* __restrict__ smem,
                                        int bm0, int bn0) {
        __nv_bfloat16* As[GSTAGES] = { smem, smem + GTILE, smem + 2 * GTILE };
        __nv_bfloat16* Bs[GSTAGES] = { smem + 3 * GTILE, smem + 4 * GTILE, smem + 5 * GTILE };

        auto issue = [&](int kt, int buf) {
            int row  = tid >> 1;                    // 0..127
            int half = tid & 1;                     // 16B chunk within 32B row
            const uint16_t* srcA = A  + (size_t)(bm0 + row) * HDIM + kt * BK + half * 8;
            const uint16_t* srcB = Bw + (size_t)(bn0 + row) * HDIM + kt * BK + half * 8;
            uint32_t dA = (uint32_t)__cvta_generic_to_shared(As[buf] + row * GST + half * 8);
            uint32_t dB = (uint32_t)__cvta_generic_to_shared(Bs[buf] + row * GST + half * 8);
            CP_ASYNC16(dA, srcA);
            CP_ASYNC16(dB, srcB);
            CP_COMMIT();
        };

        const int NT = HDIM / BK;   // 64
        issue(0, 0);
        issue(1, 1);
        for (int kt = 0; kt < NT; kt++) {
            if (kt + 1 < NT) {
                asm volatile("cp.async.wait_group 1;\n");
            } else {
                asm volatile("cp.async.wait_group 0;\n");
            }
            __syncthreads();
            if (kt + 2 < NT) issue(kt + 2, (kt + 2) % GSTAGES);

            const __nv_bfloat16* pa = As[kt % GSTAGES];
            const __nv_bfloat16* pb = Bs[kt % GSTAGES];
            uint32_t af[4][4], bf_[4][2];
            #pragma unroll
            for (int mi = 0; mi < 4; mi++) {
                int rm = wm * 64 + mi * 16;
                af[mi][0] = *(const uint32_t*)(pa + (rm + g) * GST + 2 * t);
                af[mi][1] = *(const uint32_t*)(pa + (rm + g + 8) * GST + 2 * t);
                af[mi][2] = *(const uint32_t*)(pa + (rm + g) * GST + 2 * t + 8);
                af[mi][3] = *(const uint32_t*)(pa + (rm + g + 8) * GST + 2 * t + 8);
            }
            #pragma unroll
            for (int ni = 0; ni < 4; ni++) {
                int rn = wn * 32 + ni * 8;
                bf_[ni][0] = *(const uint32_t*)(pb + (rn + g) * GST + 2 * t);
                bf_[ni][1] = *(const uint32_t*)(pb + (rn + g) * GST + 2 * t + 8);
            }
            #pragma unroll
            for (int mi = 0; mi < 4; mi++)
                #pragma unroll
                for (int ni = 0; ni < 4; ni++) mma_bf16(acc[mi][ni], af[mi], bf_[ni]);
        }
    }
};

__global__ __launch_bounds__(256) void gemm_qkv(
    const uint16_t* __restrict__ A,
    const uint16_t* __restrict__ Wq, const uint16_t* __restrict__ Wk,
    const uint16_t* __restrict__ Wv,
    uint16_t* __restrict__ Oq, uint16_t* __restrict__ Ok, uint16_t* __restrict__ Ov) {
    extern __shared__ __align__(16) __nv_bfloat16 gsm[];
    int z = blockIdx.z;
    const uint16_t* Bw = (z == 0) ? Wq : (z == 1) ? Wk : Wv;
    int bm0 = blockIdx.y * BM, bn0 = blockIdx.x * BN;

    GemmCore core;
    core.init(threadIdx.x);
    core.run(A, Bw, gsm, bm0, bn0);

    float sc = (z == 0) ? 0.125f : 1.0f;   // fold 1/sqrt(64) into Q (exact in bf16)
    #pragma unroll
    for (int mi = 0; mi < 4; mi++) {
        #pragma unroll
        for (int ni = 0; ni < 4; ni++) {
            int row0 = bm0 + core.wm * 64 + mi * 16 + core.g;
            int col0 = bn0 + core.wn * 32 + ni * 8 + 2 * core.t;
            int b = row0 >> 11, s0 = row0 & (SEQ - 1);
            int h = col0 >> 6,  hd = col0 & 63;
            float* a = core.acc[mi][ni];
            if (z != 2) {
                // Q,K: [bh][s][hd], hd pair contiguous -> packed 4B stores
                uint16_t* Cout = (z == 0) ? Oq : Ok;
                uint16_t* base = Cout + (((size_t)(b * NHEADS + h) * SEQ) << 6) + hd;
                *(uint32_t*)(base + ((size_t)s0 << 6))       = f2bf2(a[0] * sc, a[1] * sc);
                *(uint32_t*)(base + ((size_t)(s0 + 8) << 6)) = f2bf2(a[2] * sc, a[3] * sc);
            } else {
                // V transposed: [bh][hd][s] -> scalar bf16 stores
                uint16_t* vb = Ov + ((size_t)(b * NHEADS + h) * 64 + hd) * SEQ;
                vb[s0]            = f2bf(a[0]);
                vb[SEQ + s0]      = f2bf(a[1]);     // hd+1 row
                vb[s0 + 8]        = f2bf(a[2]);
                vb[SEQ + s0 + 8]  = f2bf(a[3]);
            }
        }
    }
}

__global__ __launch_bounds__(256) void gemm_oproj(
    const uint16_t* __restrict__ A, const uint16_t* __restrict__ Bw,
    float* __restrict__ Cout,
    const float* __restrict__ bias, const float* __restrict__ resid) {
    extern __shared__ __align__(16) __nv_bfloat16 gsm[];
    int bm0 = blockIdx.y * BM, bn0 = blockIdx.x * BN;

    GemmCore core;
    core.init(threadIdx.x);
    core.run(A, Bw, gsm, bm0, bn0);

    #pragma unroll
    for (int mi = 0; mi < 4; mi++) {
        #pragma unroll
        for (int ni = 0; ni < 4; ni++) {
            int row0 = bm0 + core.wm * 64 + mi * 16 + core.g;
            int col0 = bn0 + core.wn * 32 + ni * 8 + 2 * core.t;
            size_t i0 = (size_t)row0 * HDIM + col0;
            size_t i1 = (size_t)(row0 + 8) * HDIM + col0;
            float2 b2 = *(const float2*)(bias + col0);
            float2 r0 = *(const float2*)(resid + i0);
            float2 r1 = *(const float2*)(resid + i1);
            float* a = core.acc[mi][ni];
            float2 o0, o1;
            o0.x = a[0] + b2.x + r0.x;
            o0.y = a[1] + b2.y + r0.y;
            o1.x = a[2] + b2.x + r1.x;
            o1.y = a[3] + b2.y + r1.y;
            *(float2*)(Cout + i0) = o0;
            *(float2*)(Cout + i1) = o1;
        }
    }
}

// ---------------- flash attention: BQ=128, BKV=64, HD=64, 8 warps, bf16 ----------
// K: [kv][hd] tiles; V: [hd][kv] tiles (from transposed g_v); P: [q][kv] bf16.
// Row stride 72 bf16 = 144 B -> LDS.32 frag loads conflict-free (banks 4g+t).
// Double-buffered cp.async, one __syncthreads per KV iteration.
#define BQ  128
#define BKV 64
#define FS  72                                   // bf16 units per SMEM row
#define FLASH_SMEM ((2*64*FS + 2*64*FS + 128*FS) * 2)   // 55296 B

__global__ __launch_bounds__(256) void flash_kernel(
    const uint16_t* __restrict__ Qb, const uint16_t* __restrict__ Kb,
    const uint16_t* __restrict__ Vb, uint16_t* __restrict__ Ob) {
    extern __shared__ __align__(16) __nv_bfloat16 fsm[];
    __nv_bfloat16* Ksm[2] = { fsm, fsm + 64 * FS };
    __nv_bfloat16* Vsm[2] = { fsm + 2 * 64 * FS, fsm + 3 * 64 * FS };
    __nv_bfloat16* Psm    = fsm + 4 * 64 * FS;   // [128][FS] (Q stage, then P)

    int tid = threadIdx.x, warp = tid >> 5, lane = tid & 31;
    int g = lane >> 2, t = lane & 3;
    int bh = blockIdx.y, qt = blockIdx.x;
    int r0 = warp * 16;

    const uint16_t* Qp = Qb + ((size_t)bh * SEQ + qt * BQ) * HEADD;   // [s][hd]
    const uint16_t* Kp = Kb + (size_t)bh * SEQ * HEADD;               // [s][hd]
    const uint16_t* Vp = Vb + (size_t)bh * HEADD * SEQ;               // [hd][s]

    auto loadKV = [&](int kt, int buf) {
        #pragma unroll
        for (int j = 0; j < 2; j++) {
            int f = tid + j * 256;      // 512 chunks of 16B = 64 rows x 128B
            int row = f >> 3, c = f & 7;
            const uint16_t* srcK = Kp + (size_t)(kt * BKV + row) * HEADD + c * 8;
            const uint16_t* srcV = Vp + (size_t)row * SEQ + kt * BKV + c * 8;
            uint32_t dK = (uint32_t)__cvta_generic_to_shared(Ksm[buf] + row * FS + c * 8);
            uint32_t dV = (uint32_t)__cvta_generic_to_shared(Vsm[buf] + row * FS + c * 8);
            CP_ASYNC16(dK, srcK);
            CP_ASYNC16(dV, srcV);
        }
        CP_COMMIT();
    };

    loadKV(0, 0);

    // stage Q tile (128 x 64 bf16) into Psm while first K/V flies
    #pragma unroll
    for (int j = 0; j < 4; j++) {
        int f = tid + j * 256;          // 1024 chunks of 16B
        int row = f >> 3, c = f & 7;
        *(uint4*)(Psm + row * FS + c * 8) = *(const uint4*)(Qp + (size_t)row * HEADD + c * 8);
    }
    __syncthreads();
    // Q A-fragments (pre-scaled in gemm_qkv): 4 K-steps of 16
    uint32_t qa[4][4];
    #pragma unroll
    for (int ks = 0; ks < 4; ks++) {
        int kk = ks * 16;
        qa[ks][0] = *(const uint32_t*)(Psm + (r0 + g) * FS + kk + 2 * t);
        qa[ks][1] = *(const uint32_t*)(Psm + (r0 + g + 8) * FS + kk + 2 * t);
        qa[ks][2] = *(const uint32_t*)(Psm + (r0 + g) * FS + kk + 2 * t + 8);
        qa[ks][3] = *(const uint32_t*)(Psm + (r0 + g + 8) * FS + kk + 2 * t + 8);
    }
    // Psm rows are warp-private from here on: no block barrier needed

    float o[8][4];
    #pragma unroll
    for (int ni = 0; ni < 8; ni++)
        #pragma unroll
        for (int j = 0; j < 4; j++) o[ni][j] = 0.f;
    float m0 = -1e30f, m1 = -1e30f, l0 = 0.f, l1 = 0.f;

    const int NT = SEQ / BKV;   // 32
    for (int kt = 0; kt < NT; kt++) {
        asm volatile("cp.async.wait_group 0;\n");
        __syncthreads();
        if (kt + 1 < NT) loadKV(kt + 1, (kt + 1) & 1);

        const __nv_bfloat16* Kc = Ksm[kt & 1];
        const __nv_bfloat16* Vc = Vsm[kt & 1];

        // S = Q * K^T  (16 x 64 per warp), 4 K-steps x 8 n-groups
        float s[8][4];
        #pragma unroll
        for (int ni = 0; ni < 8; ni++)
            #pragma unroll
            for (int j = 0; j < 4; j++) s[ni][j] = 0.f;
        #pragma unroll
        for (int ks = 0; ks < 4; ks++) {
            int kk = ks * 16;
            #pragma unroll
            for (int ni = 0; ni < 8; ni++) {
                uint32_t bf_[2];
                bf_[0] = *(const uint32_t*)(Kc + (ni * 8 + g) * FS + kk + 2 * t);
                bf_[1] = *(const uint32_t*)(Kc + (ni * 8 + g) * FS + kk + 2 * t + 8);
                mma_bf16(s[ni], qa[ks], bf_);
            }
        }

        // online softmax (rows g, g+8); P stored bf16 packed pairs
        float mx0 = -1e30f, mx1 = -1e30f;
        #pragma unroll
        for (int ni = 0; ni < 8; ni++) {
            mx0 = fmaxf(mx0, fmaxf(s[ni][0], s[ni][1]));
            mx1 = fmaxf(mx1, fmaxf(s[ni][2], s[ni][3]));
        }
        mx0 = fmaxf(mx0, __shfl_xor_sync(0xffffffffu, mx0, 1));
        mx0 = fmaxf(mx0, __shfl_xor_sync(0xffffffffu, mx0, 2));
        mx1 = fmaxf(mx1, __shfl_xor_sync(0xffffffffu, mx1, 1));
        mx1 = fmaxf(mx1, __shfl_xor_sync(0xffffffffu, mx1, 2));
        float mn0 = fmaxf(m0, mx0), mn1 = fmaxf(m1, mx1);
        float al0 = __expf(m0 - mn0), al1 = __expf(m1 - mn1);
        float sum0 = 0.f, sum1 = 0.f;
        #pragma unroll
        for (int ni = 0; ni < 8; ni++) {
            float p0 = __expf(s[ni][0] - mn0);
            float p1 = __expf(s[ni][1] - mn0);
            float p2 = __expf(s[ni][2] - mn1);
            float p3 = __expf(s[ni][3] - mn1);
            sum0 += p0 + p1;
            sum1 += p2 + p3;
            *(uint32_t*)(Psm + (r0 + g) * FS + ni * 8 + 2 * t)     = f2bf2(p0, p1);
            *(uint32_t*)(Psm + (r0 + g + 8) * FS + ni * 8 + 2 * t) = f2bf2(p2, p3);
        }
        sum0 += __shfl_xor_sync(0xffffffffu, sum0, 1);
        sum0 += __shfl_xor_sync(0xffffffffu, sum0, 2);
        sum1 += __shfl_xor_sync(0xffffffffu, sum1, 1);
        sum1 += __shfl_xor_sync(0xffffffffu, sum1, 2);
        l0 = l0 * al0 + sum0;
        l1 = l1 * al1 + sum1;
        m0 = mn0; m1 = mn1;
        #pragma unroll
        for (int ni = 0; ni < 8; ni++) {
            o[ni][0] *= al0; o[ni][1] *= al0;
            o[ni][2] *= al1; o[ni][3] *= al1;
        }
        __syncwarp();   // Psm rows warp-private: warp ordering suffices

        // O += P * V   (V tile is [hd][kv]: kv pairs contiguous for B-frags)
        #pragma unroll
        for (int ks = 0; ks < 4; ks++) {
            int kk = ks * 16;
            uint32_t pf[4];
            pf[0] = *(const uint32_t*)(Psm + (r0 + g) * FS + kk + 2 * t);
            pf[1] = *(const uint32_t*)(Psm + (r0 + g + 8) * FS + kk + 2 * t);
            pf[2] = *(const uint32_t*)(Psm + (r0 + g) * FS + kk + 2 * t + 8);
            pf[3] = *(const uint32_t*)(Psm + (r0 + g + 8) * FS + kk + 2 * t + 8);
            #pragma unroll
            for (int ni = 0; ni < 8; ni++) {
                uint32_t vf[2];
                vf[0] = *(const uint32_t*)(Vc + (ni * 8 + g) * FS + kk + 2 * t);
                vf[1] = *(const uint32_t*)(Vc + (ni * 8 + g) * FS + kk + 2 * t + 8);
                mma_bf16(o[ni], pf, vf);
            }
        }
        // next iteration's barrier orders buffer reuse
    }

    // epilogue: normalize; write g_att bf16 (feeds O-proj A operand)
    float i0 = 1.0f / l0, i1 = 1.0f / l1;
    int b = bh / NHEADS, h = bh % NHEADS;
    int tok0 = b * SEQ + qt * BQ + r0;
    #pragma unroll
    for (int ni = 0; ni < 8; ni++) {
        int colb = h * 64 + ni * 8 + 2 * t;
        size_t ia = (size_t)(tok0 + g) * HDIM + colb;
        size_t ib = (size_t)(tok0 + g + 8) * HDIM + colb;
        *(uint32_t*)(Ob + ia) = f2bf2(o[ni][0] * i0, o[ni][1] * i0);
        *(uint32_t*)(Ob + ib) = f2bf2(o[ni][2] * i1, o[ni][3] * i1);
    }
}

// ---------------- launch ----------------
extern "C" void kernel_launch(void* const* d_in, const int* in_sizes, int n_in,
                              void* d_out, int out_size) {
    const float* x     = (const float*)d_in[0];
    const float* Wq    = (const float*)d_in[1];
    const float* Wk    = (const float*)d_in[2];
    const float* Wv    = (const float*)d_in[3];
    const float* Wo    = (const float*)d_in[4];
    const float* bo    = (const float*)d_in[5];
    const float* gamma = (const float*)d_in[6];
    const float* beta  = (const float*)d_in[7];
    float* out = (float*)d_out;

    uint16_t *p_xn, *p_q, *p_k, *p_v, *p_att, *p_wq, *p_wk, *p_wv, *p_wo;
    cudaGetSymbolAddress((void**)&p_xn, g_xn);
    cudaGetSymbolAddress((void**)&p_q, g_q);
    cudaGetSymbolAddress((void**)&p_k, g_k);
    cudaGetSymbolAddress((void**)&p_v, g_v);
    cudaGetSymbolAddress((void**)&p_att, g_att);
    cudaGetSymbolAddress((void**)&p_wq, g_wq);
    cudaGetSymbolAddress((void**)&p_wk, g_wk);
    cudaGetSymbolAddress((void**)&p_wv, g_wv);
    cudaGetSymbolAddress((void**)&p_wo, g_wo);

    cudaFuncSetAttribute(flash_kernel, cudaFuncAttributeMaxDynamicSharedMemorySize, FLASH_SMEM);
    cudaFuncSetAttribute(gemm_qkv,   cudaFuncAttributeMaxDynamicSharedMemorySize, GEMM_SMEM);
    cudaFuncSetAttribute(gemm_oproj, cudaFuncAttributeMaxDynamicSharedMemorySize, GEMM_SMEM);

    prep_kernel<<<PREP_BLOCKS, 256>>>(Wq, Wk, Wv, Wo, p_wq, p_wk, p_wv, p_wo,
                                      x, gamma, beta, p_xn);

    dim3 gq(HDIM / BN, MTOK / BM, 3);   // (8, 32, 3) fused QKV
    gemm_qkv<<<gq, 256, GEMM_SMEM>>>(p_xn, p_wq, p_wk, p_wv, p_q, p_k, p_v);

    flash_kernel<<<dim3(SEQ / BQ, BATCH * NHEADS), 256, FLASH_SMEM>>>(p_q, p_k, p_v, p_att);

    dim3 go(HDIM / BN, MTOK / BM);      // (8, 32)
    gemm_oproj<<<go, 256, GEMM_SMEM>>>(p_att, p_wo, out, bo, x);
}

// round 11
// speedup vs baseline: 2.1051x; 1.4397x over previous
#include <cuda_runtime.h>
#include <cuda_bf16.h>
#include <cstdint>

#define HDIM   1024
#define NHEADS 16
#define HEADD  64
#define BATCH  2
#define SEQ    2048
#define MTOK   (BATCH*SEQ)     // 4096 tokens

// ---------------- scratch (static device memory; no allocations) ----------------
__device__ __align__(16) uint16_t g_xn[MTOK*HDIM];                 // LN out, bf16
__device__ __align__(16) uint16_t g_q [BATCH*NHEADS*SEQ*HEADD];    // [bh][s][hd], pre-scaled 0.125
__device__ __align__(16) uint16_t g_k [BATCH*NHEADS*SEQ*HEADD];    // [bh][s][hd]
__device__ __align__(16) uint16_t g_v [BATCH*NHEADS*HEADD*SEQ];    // [bh][hd][s]  TRANSPOSED
__device__ __align__(16) uint16_t g_att[MTOK*HDIM];                // [tok][feat], bf16
__device__ __align__(16) uint16_t g_wq[HDIM*HDIM], g_wk[HDIM*HDIM];
__device__ __align__(16) uint16_t g_wv[HDIM*HDIM], g_wo[HDIM*HDIM];

// ---------------- helpers ----------------
__device__ __forceinline__ uint32_t f2bf2(float lo, float hi) {
    __nv_bfloat162 h = __floats2bfloat162_rn(lo, hi);
    return *reinterpret_cast<uint32_t*>(&h);
}
__device__ __forceinline__ uint16_t f2bf(float v) {
    __nv_bfloat16 h = __float2bfloat16_rn(v);
    return *reinterpret_cast<uint16_t*>(&h);
}

// bf16 m16n8k16: A={a0..a3}, B={b0,b1}, C=f32x4
__device__ __forceinline__ void mma_bf16(float* c, const uint32_t* a, const uint32_t* b) {
    asm volatile(
        "mma.sync.aligned.m16n8k16.row.col.f32.bf16.bf16.f32 "
        "{%0,%1,%2,%3}, {%4,%5,%6,%7}, {%8,%9}, {%0,%1,%2,%3};\n"
        : "+f"(c[0]), "+f"(c[1]), "+f"(c[2]), "+f"(c[3])
        : "r"(a[0]), "r"(a[1]), "r"(a[2]), "r"(a[3]), "r"(b[0]), "r"(b[1]));
}

// ldmatrix x4: loads four 8x8 b16 matrices; sub-matrix j -> reg j, assigned by
// lane-address groups (lanes 0-7 -> sub0, 8-15 -> sub1, 16-23 -> sub2, 24-31 -> sub3).
__device__ __forceinline__ void ldsm4(uint32_t* r, const __nv_bfloat16* p) {
    uint32_t addr = (uint32_t)__cvta_generic_to_shared(p);
    asm volatile("ldmatrix.sync.aligned.m8n8.x4.shared.b16 {%0,%1,%2,%3}, [%4];"
        : "=r"(r[0]), "=r"(r[1]), "=r"(r[2]), "=r"(r[3]) : "r"(addr));
}

#define CP_ASYNC16(dst_u32, src_ptr) \
    asm volatile("cp.async.cg.shared.global [%0], [%1], 16;\n" :: "r"(dst_u32), "l"(src_ptr))
#define CP_COMMIT() asm volatile("cp.async.commit_group;\n")

// Per-lane ldmatrix address components.
// A-style (16x16 tile -> a0..a3):  lanes 0-7 rows 0-7 col 0 | 8-15 rows 8-15 col 0
//                                | 16-23 rows 0-7 col 8 | 24-31 rows 8-15 col 8
// B-style (two 8-row n-groups)  :  lanes 0-7 rows 0-7 col 0 | 8-15 rows 0-7 col 8
//                                | 16-23 rows 8-15 col 0 | 24-31 rows 8-15 col 8
//   -> regs {b0_even, b1_even, b0_odd, b1_odd}
#define LDSM_A_ROW(l) (((l) & 7) + (((l) >> 3) & 1) * 8)
#define LDSM_A_COL(l) (((l) >> 4) * 8)
#define LDSM_B_ROW(l) (((l) & 7) + (((l) >> 4) * 8))
#define LDSM_B_COL(l) ((((l) >> 3) & 1) * 8)

// ---------------- fused prep: weight fp32->bf16 AND LayerNorm ----------------
#define PREP_WBLOCKS 4096
#define PREP_BLOCKS  (PREP_WBLOCKS + MTOK)

__global__ __launch_bounds__(256) void prep_kernel(
    const float* __restrict__ wa, const float* __restrict__ wb,
    const float* __restrict__ wc, const float* __restrict__ wd,
    uint16_t* __restrict__ oa, uint16_t* __restrict__ ob,
    uint16_t* __restrict__ oc, uint16_t* __restrict__ od,
    const float* __restrict__ x, const float* __restrict__ gamma,
    const float* __restrict__ beta, uint16_t* __restrict__ xn) {
    if (blockIdx.x < PREP_WBLOCKS) {
        int fi   = blockIdx.x * 256 + threadIdx.x;
        int sel  = fi >> 18;
        int off4 = fi & 0x3FFFF;
        int off  = off4 << 2;
        const float* s = (sel == 0) ? wa : (sel == 1) ? wb : (sel == 2) ? wc : wd;
        uint16_t* dst  = (sel == 0) ? oa : (sel == 1) ? ob : (sel == 2) ? oc : od;
        float4 v = ((const float4*)s)[off4];
        uint2 p;
        p.x = f2bf2(v.x, v.y);
        p.y = f2bf2(v.z, v.w);
        *(uint2*)(dst + off) = p;
        return;
    }
    int row = blockIdx.x - PREP_WBLOCKS;
    const float4 v = ((const float4*)(x + (size_t)row * HDIM))[threadIdx.x];
    float s  = v.x + v.y + v.z + v.w;
    float sq = v.x * v.x + v.y * v.y + v.z * v.z + v.w * v.w;
    #pragma unroll
    for (int o = 16; o; o >>= 1) {
        s  += __shfl_xor_sync(0xffffffffu, s, o);
        sq += __shfl_xor_sync(0xffffffffu, sq, o);
    }
    __shared__ float red[16];
    int w = threadIdx.x >> 5, l = threadIdx.x & 31;
    if (l == 0) { red[w] = s; red[w + 8] = sq; }
    __syncthreads();
    float ts = 0.f, tq = 0.f;
    #pragma unroll
    for (int i = 0; i < 8; i++) { ts += red[i]; tq += red[i + 8]; }
    float mu  = ts * (1.0f / HDIM);
    float var = tq * (1.0f / HDIM) - mu * mu;
    float inv = rsqrtf(var + 1e-5f);
    const float4 g4 = ((const float4*)gamma)[threadIdx.x];
    const float4 b4 = ((const float4*)beta)[threadIdx.x];
    uint2 p;
    p.x = f2bf2((v.x - mu) * inv * g4.x + b4.x, (v.y - mu) * inv * g4.y + b4.y);
    p.y = f2bf2((v.z - mu) * inv * g4.z + b4.z, (v.w - mu) * inv * g4.w + b4.w);
    *(uint2*)(xn + (size_t)row * HDIM + threadIdx.x * 4) = p;
}

// ---------------- bf16 GEMM: C = A[M,K] * B[N,K]^T ----------------
// BK=32 (2 k16 steps / tile -> 32 iterations, half the barriers), 3-stage cp.async,
// ldmatrix.x4 fragment loads. Row stride GST=40 bf16 = 80B: 8-row LDSM phases
// cover all 32 banks exactly once (conflict-free).
#define BM 128
#define BN 128
#define BK 32
#define GST 40                         // bf16 units per row (32 data + 8 pad)
#define GTILE (BM*GST)
#define GSTAGES 3
#define GEMM_SMEM (GSTAGES*2*GTILE*2)  // 61440 B dynamic

struct GemmCore {
    float acc[4][4][4];
    int tid, warp, lane, wm, wn;
    int arow, acol, brow, bcol;

    __device__ __forceinline__ void init(int tid_) {
        tid = tid_; warp = tid >> 5; lane = tid & 31;
        wm = warp >> 2; wn = warp & 3;
        arow = LDSM_A_ROW(lane); acol = LDSM_A_COL(lane);
        brow = LDSM_B_ROW(lane); bcol = LDSM_B_COL(lane);
        #pragma unroll
        for (int mi = 0; mi < 4; mi++)
            #pragma unroll
            for (int ni = 0; ni < 4; ni++)
                #pragma unroll
                for (int j = 0; j < 4; j++) acc[mi][ni][j] = 0.f;
    }

    __device__ __forceinline__ void run(const uint16_t* __restrict__ A,
                                        const uint16_t* __restrict__ Bw,
                                        __nv_bfloat16* __restrict__ smem,
                                        int bm0, int bn0) {
        __nv_bfloat16* As[GSTAGES] = { smem, smem + GTILE, smem + 2 * GTILE };
        __nv_bfloat16* Bs[GSTAGES] = { smem + 3 * GTILE, smem + 4 * GTILE, smem + 5 * GTILE };

        auto issue = [&](int kt, int buf) {
            #pragma unroll
            for (int j = 0; j < 2; j++) {
                int f = tid + j * 256;            // 512 chunks of 16B per matrix
                int row = f >> 2, c = f & 3;      // 4 chunks per 64B row
                const uint16_t* srcA = A  + (size_t)(bm0 + row) * HDIM + kt * BK + c * 8;
                const uint16_t* srcB = Bw + (size_t)(bn0 + row) * HDIM + kt * BK + c * 8;
                uint32_t dA = (uint32_t)__cvta_generic_to_shared(As[buf] + row * GST + c * 8);
                uint32_t dB = (uint32_t)__cvta_generic_to_shared(Bs[buf] + row * GST + c * 8);
                CP_ASYNC16(dA, srcA);
                CP_ASYNC16(dB, srcB);
            }
            CP_COMMIT();
        };

        const int NT = HDIM / BK;   // 32
        issue(0, 0);
        issue(1, 1);
        for (int kt = 0; kt < NT; kt++) {
            if (kt + 1 < NT) {
                asm volatile("cp.async.wait_group 1;\n");
            } else {
                asm volatile("cp.async.wait_group 0;\n");
            }
            __syncthreads();
            if (kt + 2 < NT) issue(kt + 2, (kt + 2) % GSTAGES);

            const __nv_bfloat16* pa = As[kt % GSTAGES];
            const __nv_bfloat16* pb = Bs[kt % GSTAGES];
            #pragma unroll
            for (int ks = 0; ks < 2; ks++) {
                int kk = ks * 16;
                uint32_t af[4][4], bq[2][4];
                #pragma unroll
                for (int mi = 0; mi < 4; mi++)
                    ldsm4(af[mi], pa + (size_t)(wm * 64 + mi * 16 + arow) * GST + kk + acol);
                #pragma unroll
                for (int p = 0; p < 2; p++)
                    ldsm4(bq[p], pb + (size_t)(wn * 32 + p * 16 + brow) * GST + kk + bcol);
                #pragma unroll
                for (int mi = 0; mi < 4; mi++)
                    #pragma unroll
                    for (int ni = 0; ni < 4; ni++)
                        mma_bf16(acc[mi][ni], af[mi], &bq[ni >> 1][(ni & 1) * 2]);
            }
        }
    }
};

__global__ __launch_bounds__(256) void gemm_qkv(
    const uint16_t* __restrict__ A,
    const uint16_t* __restrict__ Wq, const uint16_t* __restrict__ Wk,
    const uint16_t* __restrict__ Wv,
    uint16_t* __restrict__ Oq, uint16_t* __restrict__ Ok, uint16_t* __restrict__ Ov) {
    extern __shared__ __align__(16) __nv_bfloat16 gsm[];
    int z = blockIdx.z;
    const uint16_t* Bw = (z == 0) ? Wq : (z == 1) ? Wk : Wv;
    int bm0 = blockIdx.y * BM, bn0 = blockIdx.x * BN;

    GemmCore core;
    core.init(threadIdx.x);
    core.run(A, Bw, gsm, bm0, bn0);

    int g = core.lane >> 2, t = core.lane & 3;
    float sc = (z == 0) ? 0.125f : 1.0f;   // fold 1/sqrt(64) into Q
    #pragma unroll
    for (int mi = 0; mi < 4; mi++) {
        #pragma unroll
        for (int ni = 0; ni < 4; ni++) {
            int row0 = bm0 + core.wm * 64 + mi * 16 + g;
            int col0 = bn0 + core.wn * 32 + ni * 8 + 2 * t;
            int b = row0 >> 11, s0 = row0 & (SEQ - 1);
            int h = col0 >> 6,  hd = col0 & 63;
            float* a = core.acc[mi][ni];
            if (z != 2) {
                uint16_t* Cout = (z == 0) ? Oq : Ok;
                uint16_t* base = Cout + (((size_t)(b * NHEADS + h) * SEQ) << 6) + hd;
                *(uint32_t*)(base + ((size_t)s0 << 6))       = f2bf2(a[0] * sc, a[1] * sc);
                *(uint32_t*)(base + ((size_t)(s0 + 8) << 6)) = f2bf2(a[2] * sc, a[3] * sc);
            } else {
                uint16_t* vb = Ov + ((size_t)(b * NHEADS + h) * 64 + hd) * SEQ;
                vb[s0]            = f2bf(a[0]);
                vb[SEQ + s0]      = f2bf(a[1]);
                vb[s0 + 8]        = f2bf(a[2]);
                vb[SEQ + s0 + 8]  = f2bf(a[3]);
            }
        }
    }
}

__global__ __launch_bounds__(256) void gemm_oproj(
    const uint16_t* __restrict__ A, const uint16_t* __restrict__ Bw,
    float* __restrict__ Cout,
    const float* __restrict__ bias, const float* __restrict__ resid) {
    extern __shared__ __align__(16) __nv_bfloat16 gsm[];
    int bm0 = blockIdx.y * BM, bn0 = blockIdx.x * BN;

    GemmCore core;
    core.init(threadIdx.x);
    core.run(A, Bw, gsm, bm0, bn0);

    int g = core.lane >> 2, t = core.lane & 3;
    #pragma unroll
    for (int mi = 0; mi < 4; mi++) {
        #pragma unroll
        for (int ni = 0; ni < 4; ni++) {
            int row0 = bm0 + core.wm * 64 + mi * 16 + g;
            int col0 = bn0 + core.wn * 32 + ni * 8 + 2 * t;
            size_t i0 = (size_t)row0 * HDIM + col0;
            size_t i1 = (size_t)(row0 + 8) * HDIM + col0;
            float2 b2 = *(const float2*)(bias + col0);
            float2 r0 = *(const float2*)(resid + i0);
            float2 r1 = *(const float2*)(resid + i1);
            float* a = core.acc[mi][ni];
            float2 o0, o1;
            o0.x = a[0] + b2.x + r0.x;
            o0.y = a[1] + b2.y + r0.y;
            o1.x = a[2] + b2.x + r1.x;
            o1.y = a[3] + b2.y + r1.y;
            *(float2*)(Cout + i0) = o0;
            *(float2*)(Cout + i1) = o1;
        }
    }
}

// ---------------- flash attention: BQ=128, BKV=64, HD=64, 8 warps, bf16 ----------
// ldmatrix.x4 for qa/K/P/V fragments. Row stride FS=72 bf16 = 144B: LDSM phases
// conflict-free. Double-buffered cp.async, one __syncthreads per KV iteration.
#define BQ  128
#define BKV 64
#define FS  72
#define FLASH_SMEM ((2*64*FS + 2*64*FS + 128*FS) * 2)   // 55296 B

__global__ __launch_bounds__(256) void flash_kernel(
    const uint16_t* __restrict__ Qb, const uint16_t* __restrict__ Kb,
    const uint16_t* __restrict__ Vb, uint16_t* __restrict__ Ob) {
    extern __shared__ __align__(16) __nv_bfloat16 fsm[];
    __nv_bfloat16* Ksm[2] = { fsm, fsm + 64 * FS };
    __nv_bfloat16* Vsm[2] = { fsm + 2 * 64 * FS, fsm + 3 * 64 * FS };
    __nv_bfloat16* Psm    = fsm + 4 * 64 * FS;   // [128][FS] (Q stage, then P)

    int tid = threadIdx.x, warp = tid >> 5, lane = tid & 31;
    int g = lane >> 2, t = lane & 3;
    int bh = blockIdx.y, qt = blockIdx.x;
    int r0 = warp * 16;
    int arow = LDSM_A_ROW(lane), acol = LDSM_A_COL(lane);
    int brow = LDSM_B_ROW(lane), bcol = LDSM_B_COL(lane);

    const uint16_t* Qp = Qb + ((size_t)bh * SEQ + qt * BQ) * HEADD;   // [s][hd]
    const uint16_t* Kp = Kb + (size_t)bh * SEQ * HEADD;               // [s][hd]
    const uint16_t* Vp = Vb + (size_t)bh * HEADD * SEQ;               // [hd][s]

    auto loadKV = [&](int kt, int buf) {
        #pragma unroll
        for (int j = 0; j < 2; j++) {
            int f = tid + j * 256;
            int row = f >> 3, c = f & 7;
            const uint16_t* srcK = Kp + (size_t)(kt * BKV + row) * HEADD + c * 8;
            const uint16_t* srcV = Vp + (size_t)row * SEQ + kt * BKV + c * 8;
            uint32_t dK = (uint32_t)__cvta_generic_to_shared(Ksm[buf] + row * FS + c * 8);
            uint32_t dV = (uint32_t)__cvta_generic_to_shared(Vsm[buf] + row * FS + c * 8);
            CP_ASYNC16(dK, srcK);
            CP_ASYNC16(dV, srcV);
        }
        CP_COMMIT();
    };

    loadKV(0, 0);

    // stage Q tile into Psm while first K/V flies
    #pragma unroll
    for (int j = 0; j < 4; j++) {
        int f = tid + j * 256;
        int row = f >> 3, c = f & 7;
        *(uint4*)(Psm + row * FS + c * 8) = *(const uint4*)(Qp + (size_t)row * HEADD + c * 8);
    }
    __syncthreads();
    uint32_t qa[4][4];
    #pragma unroll
    for (int ks = 0; ks < 4; ks++)
        ldsm4(qa[ks], Psm + (size_t)(r0 + arow) * FS + ks * 16 + acol);
    // Psm rows warp-private from here on

    float o[8][4];
    #pragma unroll
    for (int ni = 0; ni < 8; ni++)
        #pragma unroll
        for (int j = 0; j < 4; j++) o[ni][j] = 0.f;
    float m0 = -1e30f, m1 = -1e30f, l0 = 0.f, l1 = 0.f;

    const int NT = SEQ / BKV;   // 32
    for (int kt = 0; kt < NT; kt++) {
        asm volatile("cp.async.wait_group 0;\n");
        __syncthreads();
        if (kt + 1 < NT) loadKV(kt + 1, (kt + 1) & 1);

        const __nv_bfloat16* Kc = Ksm[kt & 1];
        const __nv_bfloat16* Vc = Vsm[kt & 1];

        // S = Q * K^T
        float s[8][4];
        #pragma unroll
        for (int ni = 0; ni < 8; ni++)
            #pragma unroll
            for (int j = 0; j < 4; j++) s[ni][j] = 0.f;
        #pragma unroll
        for (int ks = 0; ks < 4; ks++) {
            int kk = ks * 16;
            #pragma unroll
            for (int p = 0; p < 4; p++) {
                uint32_t kq[4];
                ldsm4(kq, Kc + (size_t)(p * 16 + brow) * FS + kk + bcol);
                mma_bf16(s[2 * p],     qa[ks], kq);
                mma_bf16(s[2 * p + 1], qa[ks], kq + 2);
            }
        }

        // online softmax (rows g, g+8)
        float mx0 = -1e30f, mx1 = -1e30f;
        #pragma unroll
        for (int ni = 0; ni < 8; ni++) {
            mx0 = fmaxf(mx0, fmaxf(s[ni][0], s[ni][1]));
            mx1 = fmaxf(mx1, fmaxf(s[ni][2], s[ni][3]));
        }
        mx0 = fmaxf(mx0, __shfl_xor_sync(0xffffffffu, mx0, 1));
        mx0 = fmaxf(mx0, __shfl_xor_sync(0xffffffffu, mx0, 2));
        mx1 = fmaxf(mx1, __shfl_xor_sync(0xffffffffu, mx1, 1));
        mx1 = fmaxf(mx1, __shfl_xor_sync(0xffffffffu, mx1, 2));
        float mn0 = fmaxf(m0, mx0), mn1 = fmaxf(m1, mx1);
        float al0 = __expf(m0 - mn0), al1 = __expf(m1 - mn1);
        float sum0 = 0.f, sum1 = 0.f;
        #pragma unroll
        for (int ni = 0; ni < 8; ni++) {
            float p0 = __expf(s[ni][0] - mn0);
            float p1 = __expf(s[ni][1] - mn0);
            float p2 = __expf(s[ni][2] - mn1);
            float p3 = __expf(s[ni][3] - mn1);
            sum0 += p0 + p1;
            sum1 += p2 + p3;
            *(uint32_t*)(Psm + (r0 + g) * FS + ni * 8 + 2 * t)     = f2bf2(p0, p1);
            *(uint32_t*)(Psm + (r0 + g + 8) * FS + ni * 8 + 2 * t) = f2bf2(p2, p3);
        }
        sum0 += __shfl_xor_sync(0xffffffffu, sum0, 1);
        sum0 += __shfl_xor_sync(0xffffffffu, sum0, 2);
        sum1 += __shfl_xor_sync(0xffffffffu, sum1, 1);
        sum1 += __shfl_xor_sync(0xffffffffu, sum1, 2);
        l0 = l0 * al0 + sum0;
        l1 = l1 * al1 + sum1;
        m0 = mn0; m1 = mn1;
        #pragma unroll
        for (int ni = 0; ni < 8; ni++) {
            o[ni][0] *= al0; o[ni][1] *= al0;
            o[ni][2] *= al1; o[ni][3] *= al1;
        }
        __syncwarp();   // P written by all lanes of this warp, read via ldmatrix

        // O += P * V
        #pragma unroll
        for (int ks = 0; ks < 4; ks++) {
            int kk = ks * 16;
            uint32_t pf[4];
            ldsm4(pf, Psm + (size_t)(r0 + arow) * FS + kk + acol);
            #pragma unroll
            for (int p = 0; p < 4; p++) {
                uint32_t vq[4];
                ldsm4(vq, Vc + (size_t)(p * 16 + brow) * FS + kk + bcol);
                mma_bf16(o[2 * p],     pf, vq);
                mma_bf16(o[2 * p + 1], pf, vq + 2);
            }
        }
        // next iteration's barrier orders buffer reuse
    }

    // epilogue: normalize; write g_att bf16 (feeds O-proj A operand)
    float i0 = 1.0f / l0, i1 = 1.0f / l1;
    int b = bh / NHEADS, h = bh % NHEADS;
    int tok0 = b * SEQ + qt * BQ + r0;
    #pragma unroll
    for (int ni = 0; ni < 8; ni++) {
        int colb = h * 64 + ni * 8 + 2 * t;
        size_t ia = (size_t)(tok0 + g) * HDIM + colb;
        size_t ib = (size_t)(tok0 + g + 8) * HDIM + colb;
        *(uint32_t*)(Ob + ia) = f2bf2(o[ni][0] * i0, o[ni][1] * i0);
        *(uint32_t*)(Ob + ib) = f2bf2(o[ni][2] * i1, o[ni][3] * i1);
    }
}

// ---------------- launch ----------------
extern "C" void kernel_launch(void* const* d_in, const int* in_sizes, int n_in,
                              void* d_out, int out_size) {
    const float* x     = (const float*)d_in[0];
    const float* Wq    = (const float*)d_in[1];
    const float* Wk    = (const float*)d_in[2];
    const float* Wv    = (const float*)d_in[3];
    const float* Wo    = (const float*)d_in[4];
    const float* bo    = (const float*)d_in[5];
    const float* gamma = (const float*)d_in[6];
    const float* beta  = (const float*)d_in[7];
    float* out = (float*)d_out;

    uint16_t *p_xn, *p_q, *p_k, *p_v, *p_att, *p_wq, *p_wk, *p_wv, *p_wo;
    cudaGetSymbolAddress((void**)&p_xn, g_xn);
    cudaGetSymbolAddress((void**)&p_q, g_q);
    cudaGetSymbolAddress((void**)&p_k, g_k);
    cudaGetSymbolAddress((void**)&p_v, g_v);
    cudaGetSymbolAddress((void**)&p_att, g_att);
    cudaGetSymbolAddress((void**)&p_wq, g_wq);
    cudaGetSymbolAddress((void**)&p_wk, g_wk);
    cudaGetSymbolAddress((void**)&p_wv, g_wv);
    cudaGetSymbolAddress((void**)&p_wo, g_wo);

    cudaFuncSetAttribute(flash_kernel, cudaFuncAttributeMaxDynamicSharedMemorySize, FLASH_SMEM);
    cudaFuncSetAttribute(gemm_qkv,   cudaFuncAttributeMaxDynamicSharedMemorySize, GEMM_SMEM);
    cudaFuncSetAttribute(gemm_oproj, cudaFuncAttributeMaxDynamicSharedMemorySize, GEMM_SMEM);

    prep_kernel<<<PREP_BLOCKS, 256>>>(Wq, Wk, Wv, Wo, p_wq, p_wk, p_wv, p_wo,
                                      x, gamma, beta, p_xn);

    dim3 gq(HDIM / BN, MTOK / BM, 3);   // (8, 32, 3) fused QKV
    gemm_qkv<<<gq, 256, GEMM_SMEM>>>(p_xn, p_wq, p_wk, p_wv, p_q, p_k, p_v);

    flash_kernel<<<dim3(SEQ / BQ, BATCH * NHEADS), 256, FLASH_SMEM>>>(p_q, p_k, p_v, p_att);

    dim3 go(HDIM / BN, MTOK / BM);      // (8, 32)
    gemm_oproj<<<go, 256, GEMM_SMEM>>>(p_att, p_wo, out, bo, x);
}